// round 1
// baseline (speedup 1.0000x reference)
#include <cuda_runtime.h>

// ---------------------------------------------------------------------------
// ShiftedWindowAttention (Swin block): B=32, H=W=64, C=256, WS=8, SHIFT=4,
// HEADS=8, HEAD_DIM=32.  2048 windows x 64 tokens.
//
// Pipeline:
//   1) qkv_kernel : gathered(roll+window) X (131072x256) @ w_qkv^T (768x256)
//                   -> g_qkv[sel][w][h][t][d]
//   2) attn_kernel: per-window attention (bias + shift mask + softmax)
//                   -> g_o[w][t][c]  (c = h*32+d)
//   3) proj_kernel: g_o (131072x256) @ w_out^T (256x256) + bias,
//                   scattered (merge windows + roll back) into d_out
// ---------------------------------------------------------------------------

#define NWIN   2048
#define NTOK   131072
#define CDIM   256
#define SCALEF 0.17677669529663687f   // 32^-0.5

__device__ float g_qkv[3u * NWIN * 8 * 64 * 32];   // 402 MB
__device__ float g_o[(size_t)NTOK * CDIM];         // 134 MB

// window-token index m -> flattened source spatial index (b*4096 + ys*64 + xs).
// Same map is used for the input gather (roll -4) and the output scatter
// (merge + roll +4): both reduce to ((y+4)&63, (x+4)&63).
__device__ __forceinline__ int src_index(int m) {
    int w = m >> 6, t = m & 63;
    int b = w >> 6, wi = w & 63;
    int y  = ((wi >> 3) << 3) + (t >> 3);
    int xx = ((wi & 7) << 3) + (t & 7);
    int ys = (y + 4) & 63, xs = (xx + 4) & 63;
    return (b << 12) + (ys << 6) + xs;
}

// ---------------------------------------------------------------------------
// Kernel 1: QKV GEMM.  Block tile 128x64, K-tile 16, 256 threads, 8x4 micro.
// ---------------------------------------------------------------------------
__global__ __launch_bounds__(256) void qkv_kernel(
    const float* __restrict__ x,
    const float* __restrict__ w_qkv,
    const float* __restrict__ b_qkv)
{
    __shared__ float As[16][128];
    __shared__ float Bs[16][64];

    const int m0  = blockIdx.x * 128;
    const int n0  = blockIdx.y * 64;
    const int tid = threadIdx.x;
    const int tn  = tid & 15, tm = tid >> 4;
    const int lr  = tid >> 2, lk = (tid & 3) << 2;

    const float* a0 = x + (size_t)src_index(m0 + lr) * CDIM;
    const float* a1 = x + (size_t)src_index(m0 + lr + 64) * CDIM;
    const float* b0 = w_qkv + (size_t)(n0 + lr) * CDIM;

    float acc[8][4];
    #pragma unroll
    for (int i = 0; i < 8; i++)
        #pragma unroll
        for (int j = 0; j < 4; j++) acc[i][j] = 0.f;

    for (int k0 = 0; k0 < 256; k0 += 16) {
        float4 va0 = *(const float4*)(a0 + k0 + lk);
        float4 va1 = *(const float4*)(a1 + k0 + lk);
        float4 vb  = *(const float4*)(b0 + k0 + lk);
        As[lk+0][lr]    = va0.x; As[lk+1][lr]    = va0.y;
        As[lk+2][lr]    = va0.z; As[lk+3][lr]    = va0.w;
        As[lk+0][lr+64] = va1.x; As[lk+1][lr+64] = va1.y;
        As[lk+2][lr+64] = va1.z; As[lk+3][lr+64] = va1.w;
        Bs[lk+0][lr] = vb.x; Bs[lk+1][lr] = vb.y;
        Bs[lk+2][lr] = vb.z; Bs[lk+3][lr] = vb.w;
        __syncthreads();
        #pragma unroll
        for (int k = 0; k < 16; ++k) {
            float a[8], b[4];
            #pragma unroll
            for (int i = 0; i < 8; i++) a[i] = As[k][tm*8 + i];
            #pragma unroll
            for (int j = 0; j < 4; j++) b[j] = Bs[k][tn*4 + j];
            #pragma unroll
            for (int i = 0; i < 8; i++)
                #pragma unroll
                for (int j = 0; j < 4; j++) acc[i][j] += a[i] * b[j];
        }
        __syncthreads();
    }

    #pragma unroll
    for (int i = 0; i < 8; i++) {
        int m = m0 + tm*8 + i;
        int w = m >> 6, t = m & 63;
        #pragma unroll
        for (int j = 0; j < 4; j++) {
            int n   = n0 + tn*4 + j;
            int sel = n >> 8, h = (n >> 5) & 7, d = n & 31;
            g_qkv[((((sel*NWIN + w)*8 + h) << 6) + t)*32 + d] = acc[i][j] + b_qkv[n];
        }
    }
}

// ---------------------------------------------------------------------------
// Kernel 2: per-window attention.  1 CTA / window, 256 threads, loop heads.
// ---------------------------------------------------------------------------
__global__ __launch_bounds__(256) void attn_kernel(const float* __restrict__ pos_enc)
{
    __shared__ float sk[64][36];     // padded: conflict-free q.k row reads
    __shared__ float sv[64][32];     // broadcast access pattern, no pad needed
    __shared__ float sS[64][65];     // attention probs
    __shared__ float spe[8 * 225];   // pos_enc
    __shared__ int   sreg[64];       // shift-mask region id per token

    const int w   = blockIdx.x, tid = threadIdx.x;
    const int wi  = w & 63, wy = wi >> 3, wx = wi & 7;

    if (tid < 64) {
        int y  = wy*8 + (tid >> 3), xx = wx*8 + (tid & 7);
        int by = (y  < 56) ? 0 : (y  < 60 ? 1 : 2);
        int bx = (xx < 56) ? 0 : (xx < 60 ? 1 : 2);
        sreg[tid] = by*3 + bx;
    }
    for (int idx = tid; idx < 1800; idx += 256) spe[idx] = pos_enc[idx];

    const int i  = tid >> 2, jq = tid & 3;
    const int yi = i >> 3, xi = i & 7;

    for (int h = 0; h < 8; ++h) {
        const float* qb = g_qkv + ((w*8 + h) << 11);          // 64x32 tile
        const float* kb = qb + ((NWIN*8) << 11);
        const float* vb = kb + ((NWIN*8) << 11);
        for (int idx = tid; idx < 2048; idx += 256) {
            int r = idx >> 5, c = idx & 31;
            sk[r][c] = kb[idx];
            sv[r][c] = vb[idx];
        }
        __syncthreads();

        // q row straight from global (L1/L2 hit; read 4x per row)
        float qr[32];
        #pragma unroll
        for (int d = 0; d < 32; ++d) qr[d] = qb[(i << 5) + d];

        const int ri = sreg[i];
        float s[16];
        #pragma unroll
        for (int jj = 0; jj < 16; ++jj) {
            int j = jq*16 + jj;
            float a = 0.f;
            #pragma unroll
            for (int d = 0; d < 32; ++d) a += qr[d] * sk[j][d];
            int yj = j >> 3, xj = j & 7;
            float val = a * SCALEF + spe[h*225 + (yi - yj + 7)*15 + (xi - xj + 7)];
            if (sreg[j] != ri) val = -1e30f;
            s[jj] = val;
        }

        // softmax over 64 keys: 4 lanes per query row
        float mx = s[0];
        #pragma unroll
        for (int jj = 1; jj < 16; ++jj) mx = fmaxf(mx, s[jj]);
        mx = fmaxf(mx, __shfl_xor_sync(0xffffffffu, mx, 1));
        mx = fmaxf(mx, __shfl_xor_sync(0xffffffffu, mx, 2));
        float sum = 0.f;
        #pragma unroll
        for (int jj = 0; jj < 16; ++jj) { s[jj] = __expf(s[jj] - mx); sum += s[jj]; }
        sum += __shfl_xor_sync(0xffffffffu, sum, 1);
        sum += __shfl_xor_sync(0xffffffffu, sum, 2);
        float inv = 1.0f / sum;
        #pragma unroll
        for (int jj = 0; jj < 16; ++jj) sS[i][jq*16 + jj] = s[jj] * inv;
        __syncthreads();

        // O = P @ V : each thread does row i, 8 output dims
        float o[8] = {0,0,0,0,0,0,0,0};
        #pragma unroll 8
        for (int kk = 0; kk < 64; ++kk) {
            float p = sS[i][kk];
            #pragma unroll
            for (int dd = 0; dd < 8; ++dd) o[dd] += p * sv[kk][jq*8 + dd];
        }
        float* ob = g_o + ((size_t)w << 14) + (i << 8) + (h << 5) + (jq << 3);
        #pragma unroll
        for (int dd = 0; dd < 8; ++dd) ob[dd] = o[dd];
        __syncthreads();   // protect sS / sk / sv for next head
    }
}

// ---------------------------------------------------------------------------
// Kernel 3: output projection GEMM + merge-windows + roll-back scatter.
// ---------------------------------------------------------------------------
__global__ __launch_bounds__(256) void proj_kernel(
    const float* __restrict__ w_out,
    const float* __restrict__ b_out,
    float* __restrict__ out)
{
    __shared__ float As[16][128];
    __shared__ float Bs[16][64];

    const int m0  = blockIdx.x * 128;
    const int n0  = blockIdx.y * 64;
    const int tid = threadIdx.x;
    const int tn  = tid & 15, tm = tid >> 4;
    const int lr  = tid >> 2, lk = (tid & 3) << 2;

    const float* a0 = g_o + (size_t)(m0 + lr) * CDIM;
    const float* a1 = g_o + (size_t)(m0 + lr + 64) * CDIM;
    const float* b0 = w_out + (size_t)(n0 + lr) * CDIM;

    float acc[8][4];
    #pragma unroll
    for (int i = 0; i < 8; i++)
        #pragma unroll
        for (int j = 0; j < 4; j++) acc[i][j] = 0.f;

    for (int k0 = 0; k0 < 256; k0 += 16) {
        float4 va0 = *(const float4*)(a0 + k0 + lk);
        float4 va1 = *(const float4*)(a1 + k0 + lk);
        float4 vb  = *(const float4*)(b0 + k0 + lk);
        As[lk+0][lr]    = va0.x; As[lk+1][lr]    = va0.y;
        As[lk+2][lr]    = va0.z; As[lk+3][lr]    = va0.w;
        As[lk+0][lr+64] = va1.x; As[lk+1][lr+64] = va1.y;
        As[lk+2][lr+64] = va1.z; As[lk+3][lr+64] = va1.w;
        Bs[lk+0][lr] = vb.x; Bs[lk+1][lr] = vb.y;
        Bs[lk+2][lr] = vb.z; Bs[lk+3][lr] = vb.w;
        __syncthreads();
        #pragma unroll
        for (int k = 0; k < 16; ++k) {
            float a[8], b[4];
            #pragma unroll
            for (int i = 0; i < 8; i++) a[i] = As[k][tm*8 + i];
            #pragma unroll
            for (int j = 0; j < 4; j++) b[j] = Bs[k][tn*4 + j];
            #pragma unroll
            for (int i = 0; i < 8; i++)
                #pragma unroll
                for (int j = 0; j < 4; j++) acc[i][j] += a[i] * b[j];
        }
        __syncthreads();
    }

    #pragma unroll
    for (int i = 0; i < 8; i++) {
        int m   = m0 + tm*8 + i;
        int dst = src_index(m);     // merge + roll(+4) == same map as gather
        #pragma unroll
        for (int j = 0; j < 4; j++) {
            int n = n0 + tn*4 + j;
            out[(size_t)dst * CDIM + n] = acc[i][j] + b_out[n];
        }
    }
}

// ---------------------------------------------------------------------------
extern "C" void kernel_launch(void* const* d_in, const int* in_sizes, int n_in,
                              void* d_out, int out_size)
{
    const float* x       = (const float*)d_in[0];
    const float* w_qkv   = (const float*)d_in[1];
    const float* b_qkv   = (const float*)d_in[2];
    const float* w_out   = (const float*)d_in[3];
    const float* b_out   = (const float*)d_in[4];
    const float* pos_enc = (const float*)d_in[5];
    float* out = (float*)d_out;

    qkv_kernel<<<dim3(NTOK/128, 12), 256>>>(x, w_qkv, b_qkv);
    attn_kernel<<<NWIN, 256>>>(pos_enc);
    proj_kernel<<<dim3(NTOK/128, 4), 256>>>(w_out, b_out, out);
}

// round 6
// speedup vs baseline: 1.7439x; 1.7439x over previous
#include <cuda_runtime.h>

// ---------------------------------------------------------------------------
// ShiftedWindowAttention: B=32, H=W=64, C=256, WS=8, SHIFT=4, HEADS=8, d=32.
// Round 3: Round-2 design with two fixes:
//   (a) proj GEMM reads g_o via the device symbol (was nullptr -> illegal access)
//   (b) __align__(16) on all vector-accessed shared arrays
// ---------------------------------------------------------------------------

#define NWIN   2048
#define NTOK   131072
#define CDIM   256
#define SCALEF 0.17677669529663687f   // 32^-0.5

__device__ float g_qkv[3u * NWIN * 8 * 64 * 32];   // [sel][w][h][t][d]
__device__ float g_o[(size_t)NTOK * CDIM];         // [w*64+t][c]

typedef unsigned long long u64;

// m (window-token order) -> source spatial index (gather AND scatter map).
__device__ __forceinline__ int src_index(int m) {
    int w = m >> 6, t = m & 63;
    int b = w >> 6, wi = w & 63;
    int y  = ((wi >> 3) << 3) + (t >> 3);
    int xx = ((wi & 7) << 3) + (t & 7);
    int ys = (y + 4) & 63, xs = (xx + 4) & 63;
    return (b << 12) + (ys << 6) + xs;
}

__device__ __forceinline__ u64 dupf(float x) {
    u64 r; asm("mov.b64 %0, {%1, %1};" : "=l"(r) : "f"(x)); return r;
}
__device__ __forceinline__ void fma2(u64& d, u64 a, u64 b) {
    asm("fma.rn.f32x2 %0, %1, %2, %0;" : "+l"(d) : "l"(a), "l"(b));
}
__device__ __forceinline__ float2 unpk(u64 v) {
    float2 r; asm("mov.b64 {%0, %1}, %2;" : "=f"(r.x), "=f"(r.y) : "l"(v)); return r;
}

// ---------------------------------------------------------------------------
// GEMM: C[m][n] = sum_k A[m][k] * W[n][k] + bias[n]
// 128x128 tile, kt=16, 256 threads, 8x8 micro, f32x2 FMA, double-buffered.
// MODE 0: A = x gathered via src_index, out scattered to g_qkv layout.
// MODE 1: A = g_o (device global), out scattered spatially into d_out.
// ---------------------------------------------------------------------------
template<int MODE>
__global__ __launch_bounds__(256) void gemm_kernel(
    const float* __restrict__ Ain,
    const float* __restrict__ Wt,
    const float* __restrict__ bias,
    float* __restrict__ out)
{
    __shared__ __align__(16) float As[2][16][132];
    __shared__ __align__(16) float Bs[2][16][132];

    const int tid = threadIdx.x;
    const int m0 = blockIdx.x * 128, n0 = blockIdx.y * 128;
    const int lr = tid >> 1;           // tile row 0..127 (loader)
    const int lk = (tid & 1) * 8;      // k sub-offset 0/8 (loader)
    const int tm = tid >> 4, tn = tid & 15;

    const float* A = (MODE == 0) ? Ain : (const float*)g_o;
    const float* arow;
    if (MODE == 0) arow = A + (size_t)src_index(m0 + lr) * CDIM + lk;
    else           arow = A + (size_t)(m0 + lr) * CDIM + lk;
    const float* brow = Wt + (size_t)(n0 + lr) * CDIM + lk;

    u64 acc[4][8];
    #pragma unroll
    for (int r = 0; r < 4; r++)
        #pragma unroll
        for (int j = 0; j < 8; j++) acc[r][j] = 0ull;

    float4 pa0 = *(const float4*)(arow);
    float4 pa1 = *(const float4*)(arow + 4);
    float4 pb0 = *(const float4*)(brow);
    float4 pb1 = *(const float4*)(brow + 4);

    As[0][lk+0][lr]=pa0.x; As[0][lk+1][lr]=pa0.y; As[0][lk+2][lr]=pa0.z; As[0][lk+3][lr]=pa0.w;
    As[0][lk+4][lr]=pa1.x; As[0][lk+5][lr]=pa1.y; As[0][lk+6][lr]=pa1.z; As[0][lk+7][lr]=pa1.w;
    Bs[0][lk+0][lr]=pb0.x; Bs[0][lk+1][lr]=pb0.y; Bs[0][lk+2][lr]=pb0.z; Bs[0][lk+3][lr]=pb0.w;
    Bs[0][lk+4][lr]=pb1.x; Bs[0][lk+5][lr]=pb1.y; Bs[0][lk+6][lr]=pb1.z; Bs[0][lk+7][lr]=pb1.w;
    __syncthreads();

    #pragma unroll 1
    for (int t = 0; t < 16; ++t) {
        const int buf = t & 1;
        if (t < 15) {
            const float* an = arow + (t + 1) * 16;
            const float* bn = brow + (t + 1) * 16;
            pa0 = *(const float4*)(an);     pa1 = *(const float4*)(an + 4);
            pb0 = *(const float4*)(bn);     pb1 = *(const float4*)(bn + 4);
        }
        #pragma unroll
        for (int k = 0; k < 16; ++k) {
            ulonglong2 a01 = *(const ulonglong2*)&As[buf][k][tm * 8];
            ulonglong2 a23 = *(const ulonglong2*)&As[buf][k][tm * 8 + 4];
            float4 b0 = *(const float4*)&Bs[buf][k][tn * 8];
            float4 b1 = *(const float4*)&Bs[buf][k][tn * 8 + 4];
            u64 aa[4] = {a01.x, a01.y, a23.x, a23.y};
            u64 bb[8] = {dupf(b0.x), dupf(b0.y), dupf(b0.z), dupf(b0.w),
                         dupf(b1.x), dupf(b1.y), dupf(b1.z), dupf(b1.w)};
            #pragma unroll
            for (int r = 0; r < 4; r++)
                #pragma unroll
                for (int j = 0; j < 8; j++)
                    fma2(acc[r][j], aa[r], bb[j]);
        }
        if (t < 15) {
            const int nb = buf ^ 1;
            As[nb][lk+0][lr]=pa0.x; As[nb][lk+1][lr]=pa0.y; As[nb][lk+2][lr]=pa0.z; As[nb][lk+3][lr]=pa0.w;
            As[nb][lk+4][lr]=pa1.x; As[nb][lk+5][lr]=pa1.y; As[nb][lk+6][lr]=pa1.z; As[nb][lk+7][lr]=pa1.w;
            Bs[nb][lk+0][lr]=pb0.x; Bs[nb][lk+1][lr]=pb0.y; Bs[nb][lk+2][lr]=pb0.z; Bs[nb][lk+3][lr]=pb0.w;
            Bs[nb][lk+4][lr]=pb1.x; Bs[nb][lk+5][lr]=pb1.y; Bs[nb][lk+6][lr]=pb1.z; Bs[nb][lk+7][lr]=pb1.w;
            __syncthreads();
        }
    }

    float o[8][8];
    #pragma unroll
    for (int r = 0; r < 4; r++)
        #pragma unroll
        for (int j = 0; j < 8; j++) {
            float2 v = unpk(acc[r][j]);
            o[2*r][j] = v.x; o[2*r+1][j] = v.y;
        }

    const int nb0 = n0 + tn * 8;
    float4 bv0 = *(const float4*)(bias + nb0);
    float4 bv1 = *(const float4*)(bias + nb0 + 4);

    #pragma unroll
    for (int i = 0; i < 8; i++) {
        int m = m0 + tm * 8 + i;
        float4 lo = make_float4(o[i][0]+bv0.x, o[i][1]+bv0.y, o[i][2]+bv0.z, o[i][3]+bv0.w);
        float4 hi = make_float4(o[i][4]+bv1.x, o[i][5]+bv1.y, o[i][6]+bv1.z, o[i][7]+bv1.w);
        if (MODE == 0) {
            int w = m >> 6, tok = m & 63;
            int sel = nb0 >> 8, h = (nb0 >> 5) & 7, d0 = nb0 & 31;
            float* dst = g_qkv + ((((size_t)(sel*NWIN + w)*8 + h) << 6) + tok)*32 + d0;
            *(float4*)(dst) = lo;
            *(float4*)(dst + 4) = hi;
        } else {
            float* dst = out + (size_t)src_index(m) * CDIM + nb0;
            *(float4*)(dst) = lo;
            *(float4*)(dst + 4) = hi;
        }
    }
}

// ---------------------------------------------------------------------------
// Attention: 1 CTA / window, 256 threads, loop 8 heads.
// QK: 4x4 micro over transposed q/k tiles; PV: 2x4 micro; all f32x2 FMA.
// ---------------------------------------------------------------------------
__global__ __launch_bounds__(256) void attn_kernel(const float* __restrict__ pos_enc)
{
    __shared__ __align__(16) float sqT[32][68];   // q^T [d][t], pre-scaled
    __shared__ __align__(16) float skT[32][68];   // k^T [d][t]
    __shared__ __align__(16) float sv[64][32];    // v [t][d]
    __shared__ __align__(16) float sP[64][66];    // probs^T [k][i]
    __shared__ float spe[232];
    __shared__ int   sreg[64];

    const int w = blockIdx.x, tid = threadIdx.x;
    const int wi = w & 63, wy = wi >> 3, wx = wi & 7;

    if (tid < 64) {
        int y  = wy*8 + (tid >> 3), xx = wx*8 + (tid & 7);
        int by = (y  < 56) ? 0 : (y  < 60 ? 1 : 2);
        int bx = (xx < 56) ? 0 : (xx < 60 ? 1 : 2);
        sreg[tid] = by*3 + bx;
    }

    const int ldr_t = tid >> 2, ldr_d = (tid & 3) * 8;
    const int ti = tid >> 4, tj = tid & 15;
    const int pi = tid >> 3, pd = tid & 7;

    const int i0 = ti * 4;
    int yi[4], xi[4], ri[4];
    #pragma unroll
    for (int r = 0; r < 4; r++) { yi[r] = (i0+r) >> 3; xi[r] = (i0+r) & 7; }

    for (int h = 0; h < 8; ++h) {
        const float* qb = g_qkv + ((size_t)(w*8 + h) << 11);
        const float* kb = qb + (((size_t)NWIN*8) << 11);
        const float* vb = kb + (((size_t)NWIN*8) << 11);

        {
            float4 q0 = *(const float4*)(qb + tid*8);
            float4 q1 = *(const float4*)(qb + tid*8 + 4);
            float4 k0 = *(const float4*)(kb + tid*8);
            float4 k1 = *(const float4*)(kb + tid*8 + 4);
            float4 v0 = *(const float4*)(vb + tid*8);
            float4 v1 = *(const float4*)(vb + tid*8 + 4);
            sqT[ldr_d+0][ldr_t]=q0.x*SCALEF; sqT[ldr_d+1][ldr_t]=q0.y*SCALEF;
            sqT[ldr_d+2][ldr_t]=q0.z*SCALEF; sqT[ldr_d+3][ldr_t]=q0.w*SCALEF;
            sqT[ldr_d+4][ldr_t]=q1.x*SCALEF; sqT[ldr_d+5][ldr_t]=q1.y*SCALEF;
            sqT[ldr_d+6][ldr_t]=q1.z*SCALEF; sqT[ldr_d+7][ldr_t]=q1.w*SCALEF;
            skT[ldr_d+0][ldr_t]=k0.x; skT[ldr_d+1][ldr_t]=k0.y;
            skT[ldr_d+2][ldr_t]=k0.z; skT[ldr_d+3][ldr_t]=k0.w;
            skT[ldr_d+4][ldr_t]=k1.x; skT[ldr_d+5][ldr_t]=k1.y;
            skT[ldr_d+6][ldr_t]=k1.z; skT[ldr_d+7][ldr_t]=k1.w;
            *(float4*)&sv[ldr_t][ldr_d]     = v0;
            *(float4*)&sv[ldr_t][ldr_d + 4] = v1;
            if (tid < 225) spe[tid] = pos_enc[h*225 + tid];
        }
        __syncthreads();

        // ---- S = q @ k^T : 4x4 per thread ----
        u64 sacc[4][2];
        #pragma unroll
        for (int r = 0; r < 4; r++) { sacc[r][0] = 0ull; sacc[r][1] = 0ull; }
        #pragma unroll 8
        for (int d = 0; d < 32; ++d) {
            float4 av = *(const float4*)&sqT[d][i0];
            ulonglong2 bv = *(const ulonglong2*)&skT[d][tj*4];
            u64 aa[4] = {dupf(av.x), dupf(av.y), dupf(av.z), dupf(av.w)};
            #pragma unroll
            for (int r = 0; r < 4; r++) {
                fma2(sacc[r][0], aa[r], bv.x);
                fma2(sacc[r][1], aa[r], bv.y);
            }
        }

        float s[4][4];
        #pragma unroll
        for (int r = 0; r < 4; r++) {
            float2 v0 = unpk(sacc[r][0]), v1 = unpk(sacc[r][1]);
            s[r][0] = v0.x; s[r][1] = v0.y; s[r][2] = v1.x; s[r][3] = v1.y;
        }
        #pragma unroll
        for (int r = 0; r < 4; r++) ri[r] = sreg[i0 + r];
        #pragma unroll
        for (int c = 0; c < 4; c++) {
            int j = tj*4 + c;
            int yj = j >> 3, xj = j & 7, rj = sreg[j];
            #pragma unroll
            for (int r = 0; r < 4; r++) {
                float val = s[r][c] + spe[(yi[r]-yj+7)*15 + (xi[r]-xj+7)];
                s[r][c] = (rj != ri[r]) ? -1e30f : val;
            }
        }
        #pragma unroll
        for (int r = 0; r < 4; r++) {
            float mx = fmaxf(fmaxf(s[r][0], s[r][1]), fmaxf(s[r][2], s[r][3]));
            mx = fmaxf(mx, __shfl_xor_sync(0xffffffffu, mx, 1));
            mx = fmaxf(mx, __shfl_xor_sync(0xffffffffu, mx, 2));
            mx = fmaxf(mx, __shfl_xor_sync(0xffffffffu, mx, 4));
            mx = fmaxf(mx, __shfl_xor_sync(0xffffffffu, mx, 8));
            float sum = 0.f;
            #pragma unroll
            for (int c = 0; c < 4; c++) { s[r][c] = __expf(s[r][c] - mx); sum += s[r][c]; }
            sum += __shfl_xor_sync(0xffffffffu, sum, 1);
            sum += __shfl_xor_sync(0xffffffffu, sum, 2);
            sum += __shfl_xor_sync(0xffffffffu, sum, 4);
            sum += __shfl_xor_sync(0xffffffffu, sum, 8);
            float inv = 1.0f / sum;
            #pragma unroll
            for (int c = 0; c < 4; c++) sP[tj*4 + c][i0 + r] = s[r][c] * inv;
        }
        __syncthreads();

        // ---- O = P @ V : 2 rows x 4 d per thread ----
        u64 oacc[2][2] = {{0ull, 0ull}, {0ull, 0ull}};
        #pragma unroll 8
        for (int k = 0; k < 64; ++k) {
            float2 pv = *(const float2*)&sP[k][pi*2];
            ulonglong2 vv = *(const ulonglong2*)&sv[k][pd*4];
            u64 a0 = dupf(pv.x), a1 = dupf(pv.y);
            fma2(oacc[0][0], a0, vv.x); fma2(oacc[0][1], a0, vv.y);
            fma2(oacc[1][0], a1, vv.x); fma2(oacc[1][1], a1, vv.y);
        }
        #pragma unroll
        for (int pr = 0; pr < 2; pr++) {
            float2 r0 = unpk(oacc[pr][0]);
            float2 r1 = unpk(oacc[pr][1]);
            int i = pi*2 + pr;
            float* dst = g_o + (((size_t)(w << 6) + i) << 8) + h*32 + pd*4;
            *(float4*)dst = make_float4(r0.x, r0.y, r1.x, r1.y);
        }
        __syncthreads();
    }
}

// ---------------------------------------------------------------------------
extern "C" void kernel_launch(void* const* d_in, const int* in_sizes, int n_in,
                              void* d_out, int out_size)
{
    const float* x       = (const float*)d_in[0];
    const float* w_qkv   = (const float*)d_in[1];
    const float* b_qkv   = (const float*)d_in[2];
    const float* w_out   = (const float*)d_in[3];
    const float* b_out   = (const float*)d_in[4];
    const float* pos_enc = (const float*)d_in[5];
    float* out = (float*)d_out;

    gemm_kernel<0><<<dim3(NTOK/128, 6), 256>>>(x, w_qkv, b_qkv, nullptr);
    attn_kernel<<<NWIN, 256>>>(pos_enc);
    gemm_kernel<1><<<dim3(NTOK/128, 2), 256>>>(nullptr, w_out, b_out, out);
}

// round 7
// speedup vs baseline: 1.9831x; 1.1372x over previous
#include <cuda_runtime.h>

// ---------------------------------------------------------------------------
// ShiftedWindowAttention: B=32, H=W=64, C=256, WS=8, SHIFT=4, HEADS=8, d=32.
// Round 6: conflict-free GEMM fragment mapping (4+4 split at stride 64).
// ---------------------------------------------------------------------------

#define NWIN   2048
#define NTOK   131072
#define CDIM   256
#define SCALEF 0.17677669529663687f   // 32^-0.5

__device__ float g_qkv[3u * NWIN * 8 * 64 * 32];   // [sel][w][h][t][d]
__device__ float g_o[(size_t)NTOK * CDIM];         // [w*64+t][c]

typedef unsigned long long u64;

__device__ __forceinline__ int src_index(int m) {
    int w = m >> 6, t = m & 63;
    int b = w >> 6, wi = w & 63;
    int y  = ((wi >> 3) << 3) + (t >> 3);
    int xx = ((wi & 7) << 3) + (t & 7);
    int ys = (y + 4) & 63, xs = (xx + 4) & 63;
    return (b << 12) + (ys << 6) + xs;
}

__device__ __forceinline__ u64 dupf(float x) {
    u64 r; asm("mov.b64 %0, {%1, %1};" : "=l"(r) : "f"(x)); return r;
}
__device__ __forceinline__ void fma2(u64& d, u64 a, u64 b) {
    asm("fma.rn.f32x2 %0, %1, %2, %0;" : "+l"(d) : "l"(a), "l"(b));
}
__device__ __forceinline__ float2 unpk(u64 v) {
    float2 r; asm("mov.b64 {%0, %1}, %2;" : "=f"(r.x), "=f"(r.y) : "l"(v)); return r;
}

// ---------------------------------------------------------------------------
// GEMM: C[m][n] = sum_k A[m][k] * W[n][k] + bias[n]
// 128x128 tile, kt=16, 256 threads, 8x8 micro (two 4-wide chunks @ stride 64),
// f32x2 FMA, double-buffered smem.  Fragment reads are lane-contiguous.
// MODE 0: A = x gathered via src_index, out scattered to g_qkv layout.
// MODE 1: A = g_o (device global), out scattered spatially into d_out.
// ---------------------------------------------------------------------------
template<int MODE>
__global__ __launch_bounds__(256) void gemm_kernel(
    const float* __restrict__ Ain,
    const float* __restrict__ Wt,
    const float* __restrict__ bias,
    float* __restrict__ out)
{
    __shared__ __align__(16) float As[2][16][132];
    __shared__ __align__(16) float Bs[2][16][132];

    const int tid = threadIdx.x;
    const int m0 = blockIdx.x * 128, n0 = blockIdx.y * 128;
    const int lr = tid >> 1;           // tile row 0..127 (loader)
    const int lk = (tid & 1) * 8;      // k sub-offset 0/8 (loader)
    const int tm = tid >> 4, tn = tid & 15;

    const float* A = (MODE == 0) ? Ain : (const float*)g_o;
    const float* arow;
    if (MODE == 0) arow = A + (size_t)src_index(m0 + lr) * CDIM + lk;
    else           arow = A + (size_t)(m0 + lr) * CDIM + lk;
    const float* brow = Wt + (size_t)(n0 + lr) * CDIM + lk;

    // acc[p][j]: row pair p (m = m0 + (p>>1)*64 + tm*4 + (p&1)*2 + lane),
    //            col j     (n = n0 + (j>>2)*64 + tn*4 + (j&3))
    u64 acc[4][8];
    #pragma unroll
    for (int p = 0; p < 4; p++)
        #pragma unroll
        for (int j = 0; j < 8; j++) acc[p][j] = 0ull;

    float4 pa0 = *(const float4*)(arow);
    float4 pa1 = *(const float4*)(arow + 4);
    float4 pb0 = *(const float4*)(brow);
    float4 pb1 = *(const float4*)(brow + 4);

    As[0][lk+0][lr]=pa0.x; As[0][lk+1][lr]=pa0.y; As[0][lk+2][lr]=pa0.z; As[0][lk+3][lr]=pa0.w;
    As[0][lk+4][lr]=pa1.x; As[0][lk+5][lr]=pa1.y; As[0][lk+6][lr]=pa1.z; As[0][lk+7][lr]=pa1.w;
    Bs[0][lk+0][lr]=pb0.x; Bs[0][lk+1][lr]=pb0.y; Bs[0][lk+2][lr]=pb0.z; Bs[0][lk+3][lr]=pb0.w;
    Bs[0][lk+4][lr]=pb1.x; Bs[0][lk+5][lr]=pb1.y; Bs[0][lk+6][lr]=pb1.z; Bs[0][lk+7][lr]=pb1.w;
    __syncthreads();

    #pragma unroll 1
    for (int t = 0; t < 16; ++t) {
        const int buf = t & 1;
        if (t < 15) {
            const float* an = arow + (t + 1) * 16;
            const float* bn = brow + (t + 1) * 16;
            pa0 = *(const float4*)(an);     pa1 = *(const float4*)(an + 4);
            pb0 = *(const float4*)(bn);     pb1 = *(const float4*)(bn + 4);
        }
        #pragma unroll
        for (int k = 0; k < 16; ++k) {
            // rows: two 4-wide chunks (broadcast: address depends only on tm)
            ulonglong2 a0 = *(const ulonglong2*)&As[buf][k][tm * 4];
            ulonglong2 a1 = *(const ulonglong2*)&As[buf][k][64 + tm * 4];
            // cols: lane-contiguous 16B chunks (tn*16B) -> conflict-free
            float4 b0 = *(const float4*)&Bs[buf][k][tn * 4];
            float4 b1 = *(const float4*)&Bs[buf][k][64 + tn * 4];
            u64 aa[4] = {a0.x, a0.y, a1.x, a1.y};
            u64 bb[8] = {dupf(b0.x), dupf(b0.y), dupf(b0.z), dupf(b0.w),
                         dupf(b1.x), dupf(b1.y), dupf(b1.z), dupf(b1.w)};
            #pragma unroll
            for (int p = 0; p < 4; p++)
                #pragma unroll
                for (int j = 0; j < 8; j++)
                    fma2(acc[p][j], aa[p], bb[j]);
        }
        if (t < 15) {
            const int nb = buf ^ 1;
            As[nb][lk+0][lr]=pa0.x; As[nb][lk+1][lr]=pa0.y; As[nb][lk+2][lr]=pa0.z; As[nb][lk+3][lr]=pa0.w;
            As[nb][lk+4][lr]=pa1.x; As[nb][lk+5][lr]=pa1.y; As[nb][lk+6][lr]=pa1.z; As[nb][lk+7][lr]=pa1.w;
            Bs[nb][lk+0][lr]=pb0.x; Bs[nb][lk+1][lr]=pb0.y; Bs[nb][lk+2][lr]=pb0.z; Bs[nb][lk+3][lr]=pb0.w;
            Bs[nb][lk+4][lr]=pb1.x; Bs[nb][lk+5][lr]=pb1.y; Bs[nb][lk+6][lr]=pb1.z; Bs[nb][lk+7][lr]=pb1.w;
            __syncthreads();
        }
    }

    // o[i][j]: local row i (0..7) -> m = m0 + (i>>2)*64 + tm*4 + (i&3)
    float o[8][8];
    #pragma unroll
    for (int p = 0; p < 4; p++)
        #pragma unroll
        for (int j = 0; j < 8; j++) {
            float2 v = unpk(acc[p][j]);
            int i = (p >> 1) * 4 + (p & 1) * 2;
            o[i][j] = v.x; o[i + 1][j] = v.y;
        }

    const int cb0 = n0 + tn * 4;        // first col chunk
    const int cb1 = n0 + 64 + tn * 4;   // second col chunk
    float4 bv0 = *(const float4*)(bias + cb0);
    float4 bv1 = *(const float4*)(bias + cb1);

    #pragma unroll
    for (int i = 0; i < 8; i++) {
        int m = m0 + (i >> 2) * 64 + tm * 4 + (i & 3);
        float4 lo = make_float4(o[i][0]+bv0.x, o[i][1]+bv0.y, o[i][2]+bv0.z, o[i][3]+bv0.w);
        float4 hi = make_float4(o[i][4]+bv1.x, o[i][5]+bv1.y, o[i][6]+bv1.z, o[i][7]+bv1.w);
        if (MODE == 0) {
            int w = m >> 6, tok = m & 63;
            {   // chunk 0: 4 consecutive d within one (sel,h)
                int sel = cb0 >> 8, h = (cb0 >> 5) & 7, d0 = cb0 & 31;
                float* dst = g_qkv + ((((size_t)(sel*NWIN + w)*8 + h) << 6) + tok)*32 + d0;
                *(float4*)dst = lo;
            }
            {   // chunk 1
                int sel = cb1 >> 8, h = (cb1 >> 5) & 7, d0 = cb1 & 31;
                float* dst = g_qkv + ((((size_t)(sel*NWIN + w)*8 + h) << 6) + tok)*32 + d0;
                *(float4*)dst = hi;
            }
        } else {
            float* dst = out + (size_t)src_index(m) * CDIM;
            *(float4*)(dst + cb0) = lo;
            *(float4*)(dst + cb1) = hi;
        }
    }
}

// ---------------------------------------------------------------------------
// Attention: 1 CTA / window, 256 threads, loop 8 heads.  (unchanged)
// ---------------------------------------------------------------------------
__global__ __launch_bounds__(256) void attn_kernel(const float* __restrict__ pos_enc)
{
    __shared__ __align__(16) float sqT[32][68];
    __shared__ __align__(16) float skT[32][68];
    __shared__ __align__(16) float sv[64][32];
    __shared__ __align__(16) float sP[64][66];
    __shared__ float spe[232];
    __shared__ int   sreg[64];

    const int w = blockIdx.x, tid = threadIdx.x;
    const int wi = w & 63, wy = wi >> 3, wx = wi & 7;

    if (tid < 64) {
        int y  = wy*8 + (tid >> 3), xx = wx*8 + (tid & 7);
        int by = (y  < 56) ? 0 : (y  < 60 ? 1 : 2);
        int bx = (xx < 56) ? 0 : (xx < 60 ? 1 : 2);
        sreg[tid] = by*3 + bx;
    }

    const int ldr_t = tid >> 2, ldr_d = (tid & 3) * 8;
    const int ti = tid >> 4, tj = tid & 15;
    const int pi = tid >> 3, pd = tid & 7;

    const int i0 = ti * 4;
    int yi[4], xi[4], ri[4];
    #pragma unroll
    for (int r = 0; r < 4; r++) { yi[r] = (i0+r) >> 3; xi[r] = (i0+r) & 7; }

    for (int h = 0; h < 8; ++h) {
        const float* qb = g_qkv + ((size_t)(w*8 + h) << 11);
        const float* kb = qb + (((size_t)NWIN*8) << 11);
        const float* vb = kb + (((size_t)NWIN*8) << 11);

        {
            float4 q0 = *(const float4*)(qb + tid*8);
            float4 q1 = *(const float4*)(qb + tid*8 + 4);
            float4 k0 = *(const float4*)(kb + tid*8);
            float4 k1 = *(const float4*)(kb + tid*8 + 4);
            float4 v0 = *(const float4*)(vb + tid*8);
            float4 v1 = *(const float4*)(vb + tid*8 + 4);
            sqT[ldr_d+0][ldr_t]=q0.x*SCALEF; sqT[ldr_d+1][ldr_t]=q0.y*SCALEF;
            sqT[ldr_d+2][ldr_t]=q0.z*SCALEF; sqT[ldr_d+3][ldr_t]=q0.w*SCALEF;
            sqT[ldr_d+4][ldr_t]=q1.x*SCALEF; sqT[ldr_d+5][ldr_t]=q1.y*SCALEF;
            sqT[ldr_d+6][ldr_t]=q1.z*SCALEF; sqT[ldr_d+7][ldr_t]=q1.w*SCALEF;
            skT[ldr_d+0][ldr_t]=k0.x; skT[ldr_d+1][ldr_t]=k0.y;
            skT[ldr_d+2][ldr_t]=k0.z; skT[ldr_d+3][ldr_t]=k0.w;
            skT[ldr_d+4][ldr_t]=k1.x; skT[ldr_d+5][ldr_t]=k1.y;
            skT[ldr_d+6][ldr_t]=k1.z; skT[ldr_d+7][ldr_t]=k1.w;
            *(float4*)&sv[ldr_t][ldr_d]     = v0;
            *(float4*)&sv[ldr_t][ldr_d + 4] = v1;
            if (tid < 225) spe[tid] = pos_enc[h*225 + tid];
        }
        __syncthreads();

        u64 sacc[4][2];
        #pragma unroll
        for (int r = 0; r < 4; r++) { sacc[r][0] = 0ull; sacc[r][1] = 0ull; }
        #pragma unroll 8
        for (int d = 0; d < 32; ++d) {
            float4 av = *(const float4*)&sqT[d][i0];
            ulonglong2 bv = *(const ulonglong2*)&skT[d][tj*4];
            u64 aa[4] = {dupf(av.x), dupf(av.y), dupf(av.z), dupf(av.w)};
            #pragma unroll
            for (int r = 0; r < 4; r++) {
                fma2(sacc[r][0], aa[r], bv.x);
                fma2(sacc[r][1], aa[r], bv.y);
            }
        }

        float s[4][4];
        #pragma unroll
        for (int r = 0; r < 4; r++) {
            float2 v0 = unpk(sacc[r][0]), v1 = unpk(sacc[r][1]);
            s[r][0] = v0.x; s[r][1] = v0.y; s[r][2] = v1.x; s[r][3] = v1.y;
        }
        #pragma unroll
        for (int r = 0; r < 4; r++) ri[r] = sreg[i0 + r];
        #pragma unroll
        for (int c = 0; c < 4; c++) {
            int j = tj*4 + c;
            int yj = j >> 3, xj = j & 7, rj = sreg[j];
            #pragma unroll
            for (int r = 0; r < 4; r++) {
                float val = s[r][c] + spe[(yi[r]-yj+7)*15 + (xi[r]-xj+7)];
                s[r][c] = (rj != ri[r]) ? -1e30f : val;
            }
        }
        #pragma unroll
        for (int r = 0; r < 4; r++) {
            float mx = fmaxf(fmaxf(s[r][0], s[r][1]), fmaxf(s[r][2], s[r][3]));
            mx = fmaxf(mx, __shfl_xor_sync(0xffffffffu, mx, 1));
            mx = fmaxf(mx, __shfl_xor_sync(0xffffffffu, mx, 2));
            mx = fmaxf(mx, __shfl_xor_sync(0xffffffffu, mx, 4));
            mx = fmaxf(mx, __shfl_xor_sync(0xffffffffu, mx, 8));
            float sum = 0.f;
            #pragma unroll
            for (int c = 0; c < 4; c++) { s[r][c] = __expf(s[r][c] - mx); sum += s[r][c]; }
            sum += __shfl_xor_sync(0xffffffffu, sum, 1);
            sum += __shfl_xor_sync(0xffffffffu, sum, 2);
            sum += __shfl_xor_sync(0xffffffffu, sum, 4);
            sum += __shfl_xor_sync(0xffffffffu, sum, 8);
            float inv = 1.0f / sum;
            #pragma unroll
            for (int c = 0; c < 4; c++) sP[tj*4 + c][i0 + r] = s[r][c] * inv;
        }
        __syncthreads();

        u64 oacc[2][2] = {{0ull, 0ull}, {0ull, 0ull}};
        #pragma unroll 8
        for (int k = 0; k < 64; ++k) {
            float2 pv = *(const float2*)&sP[k][pi*2];
            ulonglong2 vv = *(const ulonglong2*)&sv[k][pd*4];
            u64 a0 = dupf(pv.x), a1 = dupf(pv.y);
            fma2(oacc[0][0], a0, vv.x); fma2(oacc[0][1], a0, vv.y);
            fma2(oacc[1][0], a1, vv.x); fma2(oacc[1][1], a1, vv.y);
        }
        #pragma unroll
        for (int pr = 0; pr < 2; pr++) {
            float2 r0 = unpk(oacc[pr][0]);
            float2 r1 = unpk(oacc[pr][1]);
            int i = pi*2 + pr;
            float* dst = g_o + (((size_t)(w << 6) + i) << 8) + h*32 + pd*4;
            *(float4*)dst = make_float4(r0.x, r0.y, r1.x, r1.y);
        }
        __syncthreads();
    }
}

// ---------------------------------------------------------------------------
extern "C" void kernel_launch(void* const* d_in, const int* in_sizes, int n_in,
                              void* d_out, int out_size)
{
    const float* x       = (const float*)d_in[0];
    const float* w_qkv   = (const float*)d_in[1];
    const float* b_qkv   = (const float*)d_in[2];
    const float* w_out   = (const float*)d_in[3];
    const float* b_out   = (const float*)d_in[4];
    const float* pos_enc = (const float*)d_in[5];
    float* out = (float*)d_out;

    gemm_kernel<0><<<dim3(NTOK/128, 6), 256>>>(x, w_qkv, b_qkv, nullptr);
    attn_kernel<<<NWIN, 256>>>(pos_enc);
    gemm_kernel<1><<<dim3(NTOK/128, 2), 256>>>(nullptr, w_out, b_out, out);
}

// round 8
// speedup vs baseline: 2.0951x; 1.0564x over previous
#include <cuda_runtime.h>

// ---------------------------------------------------------------------------
// ShiftedWindowAttention: B=32, H=W=64, C=256, WS=8, SHIFT=4, HEADS=8, d=32.
// Round 7: __launch_bounds__(256,2) on GEMMs -> 2 CTAs/SM (regs 140 -> <=128),
// covering per-k-tile sync latency.  Everything else identical to Round 6.
// ---------------------------------------------------------------------------

#define NWIN   2048
#define NTOK   131072
#define CDIM   256
#define SCALEF 0.17677669529663687f   // 32^-0.5

__device__ float g_qkv[3u * NWIN * 8 * 64 * 32];   // [sel][w][h][t][d]
__device__ float g_o[(size_t)NTOK * CDIM];         // [w*64+t][c]

typedef unsigned long long u64;

__device__ __forceinline__ int src_index(int m) {
    int w = m >> 6, t = m & 63;
    int b = w >> 6, wi = w & 63;
    int y  = ((wi >> 3) << 3) + (t >> 3);
    int xx = ((wi & 7) << 3) + (t & 7);
    int ys = (y + 4) & 63, xs = (xx + 4) & 63;
    return (b << 12) + (ys << 6) + xs;
}

__device__ __forceinline__ u64 dupf(float x) {
    u64 r; asm("mov.b64 %0, {%1, %1};" : "=l"(r) : "f"(x)); return r;
}
__device__ __forceinline__ void fma2(u64& d, u64 a, u64 b) {
    asm("fma.rn.f32x2 %0, %1, %2, %0;" : "+l"(d) : "l"(a), "l"(b));
}
__device__ __forceinline__ float2 unpk(u64 v) {
    float2 r; asm("mov.b64 {%0, %1}, %2;" : "=f"(r.x), "=f"(r.y) : "l"(v)); return r;
}

// ---------------------------------------------------------------------------
// GEMM: C[m][n] = sum_k A[m][k] * W[n][k] + bias[n]
// 128x128 tile, kt=16, 256 threads, 8x8 micro (two 4-wide chunks @ stride 64),
// f32x2 FMA, double-buffered smem, 2 CTAs/SM.
// MODE 0: A = x gathered via src_index, out scattered to g_qkv layout.
// MODE 1: A = g_o (device global), out scattered spatially into d_out.
// ---------------------------------------------------------------------------
template<int MODE>
__global__ __launch_bounds__(256, 2) void gemm_kernel(
    const float* __restrict__ Ain,
    const float* __restrict__ Wt,
    const float* __restrict__ bias,
    float* __restrict__ out)
{
    __shared__ __align__(16) float As[2][16][132];
    __shared__ __align__(16) float Bs[2][16][132];

    const int tid = threadIdx.x;
    const int m0 = blockIdx.x * 128, n0 = blockIdx.y * 128;
    const int lr = tid >> 1;           // tile row 0..127 (loader)
    const int lk = (tid & 1) * 8;      // k sub-offset 0/8 (loader)
    const int tm = tid >> 4, tn = tid & 15;

    const float* A = (MODE == 0) ? Ain : (const float*)g_o;
    const float* arow;
    if (MODE == 0) arow = A + (size_t)src_index(m0 + lr) * CDIM + lk;
    else           arow = A + (size_t)(m0 + lr) * CDIM + lk;
    const float* brow = Wt + (size_t)(n0 + lr) * CDIM + lk;

    // acc[p][j]: row pair p (m = m0 + (p>>1)*64 + tm*4 + (p&1)*2 + lane),
    //            col j     (n = n0 + (j>>2)*64 + tn*4 + (j&3))
    u64 acc[4][8];
    #pragma unroll
    for (int p = 0; p < 4; p++)
        #pragma unroll
        for (int j = 0; j < 8; j++) acc[p][j] = 0ull;

    float4 pa0 = *(const float4*)(arow);
    float4 pa1 = *(const float4*)(arow + 4);
    float4 pb0 = *(const float4*)(brow);
    float4 pb1 = *(const float4*)(brow + 4);

    As[0][lk+0][lr]=pa0.x; As[0][lk+1][lr]=pa0.y; As[0][lk+2][lr]=pa0.z; As[0][lk+3][lr]=pa0.w;
    As[0][lk+4][lr]=pa1.x; As[0][lk+5][lr]=pa1.y; As[0][lk+6][lr]=pa1.z; As[0][lk+7][lr]=pa1.w;
    Bs[0][lk+0][lr]=pb0.x; Bs[0][lk+1][lr]=pb0.y; Bs[0][lk+2][lr]=pb0.z; Bs[0][lk+3][lr]=pb0.w;
    Bs[0][lk+4][lr]=pb1.x; Bs[0][lk+5][lr]=pb1.y; Bs[0][lk+6][lr]=pb1.z; Bs[0][lk+7][lr]=pb1.w;
    __syncthreads();

    #pragma unroll 1
    for (int t = 0; t < 16; ++t) {
        const int buf = t & 1;
        if (t < 15) {
            const float* an = arow + (t + 1) * 16;
            const float* bn = brow + (t + 1) * 16;
            pa0 = *(const float4*)(an);     pa1 = *(const float4*)(an + 4);
            pb0 = *(const float4*)(bn);     pb1 = *(const float4*)(bn + 4);
        }
        #pragma unroll
        for (int k = 0; k < 16; ++k) {
            ulonglong2 a0 = *(const ulonglong2*)&As[buf][k][tm * 4];
            ulonglong2 a1 = *(const ulonglong2*)&As[buf][k][64 + tm * 4];
            float4 b0 = *(const float4*)&Bs[buf][k][tn * 4];
            float4 b1 = *(const float4*)&Bs[buf][k][64 + tn * 4];
            u64 aa[4] = {a0.x, a0.y, a1.x, a1.y};
            u64 bb[8] = {dupf(b0.x), dupf(b0.y), dupf(b0.z), dupf(b0.w),
                         dupf(b1.x), dupf(b1.y), dupf(b1.z), dupf(b1.w)};
            #pragma unroll
            for (int p = 0; p < 4; p++)
                #pragma unroll
                for (int j = 0; j < 8; j++)
                    fma2(acc[p][j], aa[p], bb[j]);
        }
        if (t < 15) {
            const int nb = buf ^ 1;
            As[nb][lk+0][lr]=pa0.x; As[nb][lk+1][lr]=pa0.y; As[nb][lk+2][lr]=pa0.z; As[nb][lk+3][lr]=pa0.w;
            As[nb][lk+4][lr]=pa1.x; As[nb][lk+5][lr]=pa1.y; As[nb][lk+6][lr]=pa1.z; As[nb][lk+7][lr]=pa1.w;
            Bs[nb][lk+0][lr]=pb0.x; Bs[nb][lk+1][lr]=pb0.y; Bs[nb][lk+2][lr]=pb0.z; Bs[nb][lk+3][lr]=pb0.w;
            Bs[nb][lk+4][lr]=pb1.x; Bs[nb][lk+5][lr]=pb1.y; Bs[nb][lk+6][lr]=pb1.z; Bs[nb][lk+7][lr]=pb1.w;
            __syncthreads();
        }
    }

    float o[8][8];
    #pragma unroll
    for (int p = 0; p < 4; p++)
        #pragma unroll
        for (int j = 0; j < 8; j++) {
            float2 v = unpk(acc[p][j]);
            int i = (p >> 1) * 4 + (p & 1) * 2;
            o[i][j] = v.x; o[i + 1][j] = v.y;
        }

    const int cb0 = n0 + tn * 4;
    const int cb1 = n0 + 64 + tn * 4;
    float4 bv0 = *(const float4*)(bias + cb0);
    float4 bv1 = *(const float4*)(bias + cb1);

    #pragma unroll
    for (int i = 0; i < 8; i++) {
        int m = m0 + (i >> 2) * 64 + tm * 4 + (i & 3);
        float4 lo = make_float4(o[i][0]+bv0.x, o[i][1]+bv0.y, o[i][2]+bv0.z, o[i][3]+bv0.w);
        float4 hi = make_float4(o[i][4]+bv1.x, o[i][5]+bv1.y, o[i][6]+bv1.z, o[i][7]+bv1.w);
        if (MODE == 0) {
            int w = m >> 6, tok = m & 63;
            {
                int sel = cb0 >> 8, h = (cb0 >> 5) & 7, d0 = cb0 & 31;
                float* dst = g_qkv + ((((size_t)(sel*NWIN + w)*8 + h) << 6) + tok)*32 + d0;
                *(float4*)dst = lo;
            }
            {
                int sel = cb1 >> 8, h = (cb1 >> 5) & 7, d0 = cb1 & 31;
                float* dst = g_qkv + ((((size_t)(sel*NWIN + w)*8 + h) << 6) + tok)*32 + d0;
                *(float4*)dst = hi;
            }
        } else {
            float* dst = out + (size_t)src_index(m) * CDIM;
            *(float4*)(dst + cb0) = lo;
            *(float4*)(dst + cb1) = hi;
        }
    }
}

// ---------------------------------------------------------------------------
// Attention: 1 CTA / window, 256 threads, loop 8 heads.  (unchanged)
// ---------------------------------------------------------------------------
__global__ __launch_bounds__(256) void attn_kernel(const float* __restrict__ pos_enc)
{
    __shared__ __align__(16) float sqT[32][68];
    __shared__ __align__(16) float skT[32][68];
    __shared__ __align__(16) float sv[64][32];
    __shared__ __align__(16) float sP[64][66];
    __shared__ float spe[232];
    __shared__ int   sreg[64];

    const int w = blockIdx.x, tid = threadIdx.x;
    const int wi = w & 63, wy = wi >> 3, wx = wi & 7;

    if (tid < 64) {
        int y  = wy*8 + (tid >> 3), xx = wx*8 + (tid & 7);
        int by = (y  < 56) ? 0 : (y  < 60 ? 1 : 2);
        int bx = (xx < 56) ? 0 : (xx < 60 ? 1 : 2);
        sreg[tid] = by*3 + bx;
    }

    const int ldr_t = tid >> 2, ldr_d = (tid & 3) * 8;
    const int ti = tid >> 4, tj = tid & 15;
    const int pi = tid >> 3, pd = tid & 7;

    const int i0 = ti * 4;
    int yi[4], xi[4], ri[4];
    #pragma unroll
    for (int r = 0; r < 4; r++) { yi[r] = (i0+r) >> 3; xi[r] = (i0+r) & 7; }

    for (int h = 0; h < 8; ++h) {
        const float* qb = g_qkv + ((size_t)(w*8 + h) << 11);
        const float* kb = qb + (((size_t)NWIN*8) << 11);
        const float* vb = kb + (((size_t)NWIN*8) << 11);

        {
            float4 q0 = *(const float4*)(qb + tid*8);
            float4 q1 = *(const float4*)(qb + tid*8 + 4);
            float4 k0 = *(const float4*)(kb + tid*8);
            float4 k1 = *(const float4*)(kb + tid*8 + 4);
            float4 v0 = *(const float4*)(vb + tid*8);
            float4 v1 = *(const float4*)(vb + tid*8 + 4);
            sqT[ldr_d+0][ldr_t]=q0.x*SCALEF; sqT[ldr_d+1][ldr_t]=q0.y*SCALEF;
            sqT[ldr_d+2][ldr_t]=q0.z*SCALEF; sqT[ldr_d+3][ldr_t]=q0.w*SCALEF;
            sqT[ldr_d+4][ldr_t]=q1.x*SCALEF; sqT[ldr_d+5][ldr_t]=q1.y*SCALEF;
            sqT[ldr_d+6][ldr_t]=q1.z*SCALEF; sqT[ldr_d+7][ldr_t]=q1.w*SCALEF;
            skT[ldr_d+0][ldr_t]=k0.x; skT[ldr_d+1][ldr_t]=k0.y;
            skT[ldr_d+2][ldr_t]=k0.z; skT[ldr_d+3][ldr_t]=k0.w;
            skT[ldr_d+4][ldr_t]=k1.x; skT[ldr_d+5][ldr_t]=k1.y;
            skT[ldr_d+6][ldr_t]=k1.z; skT[ldr_d+7][ldr_t]=k1.w;
            *(float4*)&sv[ldr_t][ldr_d]     = v0;
            *(float4*)&sv[ldr_t][ldr_d + 4] = v1;
            if (tid < 225) spe[tid] = pos_enc[h*225 + tid];
        }
        __syncthreads();

        u64 sacc[4][2];
        #pragma unroll
        for (int r = 0; r < 4; r++) { sacc[r][0] = 0ull; sacc[r][1] = 0ull; }
        #pragma unroll 8
        for (int d = 0; d < 32; ++d) {
            float4 av = *(const float4*)&sqT[d][i0];
            ulonglong2 bv = *(const ulonglong2*)&skT[d][tj*4];
            u64 aa[4] = {dupf(av.x), dupf(av.y), dupf(av.z), dupf(av.w)};
            #pragma unroll
            for (int r = 0; r < 4; r++) {
                fma2(sacc[r][0], aa[r], bv.x);
                fma2(sacc[r][1], aa[r], bv.y);
            }
        }

        float s[4][4];
        #pragma unroll
        for (int r = 0; r < 4; r++) {
            float2 v0 = unpk(sacc[r][0]), v1 = unpk(sacc[r][1]);
            s[r][0] = v0.x; s[r][1] = v0.y; s[r][2] = v1.x; s[r][3] = v1.y;
        }
        #pragma unroll
        for (int r = 0; r < 4; r++) ri[r] = sreg[i0 + r];
        #pragma unroll
        for (int c = 0; c < 4; c++) {
            int j = tj*4 + c;
            int yj = j >> 3, xj = j & 7, rj = sreg[j];
            #pragma unroll
            for (int r = 0; r < 4; r++) {
                float val = s[r][c] + spe[(yi[r]-yj+7)*15 + (xi[r]-xj+7)];
                s[r][c] = (rj != ri[r]) ? -1e30f : val;
            }
        }
        #pragma unroll
        for (int r = 0; r < 4; r++) {
            float mx = fmaxf(fmaxf(s[r][0], s[r][1]), fmaxf(s[r][2], s[r][3]));
            mx = fmaxf(mx, __shfl_xor_sync(0xffffffffu, mx, 1));
            mx = fmaxf(mx, __shfl_xor_sync(0xffffffffu, mx, 2));
            mx = fmaxf(mx, __shfl_xor_sync(0xffffffffu, mx, 4));
            mx = fmaxf(mx, __shfl_xor_sync(0xffffffffu, mx, 8));
            float sum = 0.f;
            #pragma unroll
            for (int c = 0; c < 4; c++) { s[r][c] = __expf(s[r][c] - mx); sum += s[r][c]; }
            sum += __shfl_xor_sync(0xffffffffu, sum, 1);
            sum += __shfl_xor_sync(0xffffffffu, sum, 2);
            sum += __shfl_xor_sync(0xffffffffu, sum, 4);
            sum += __shfl_xor_sync(0xffffffffu, sum, 8);
            float inv = 1.0f / sum;
            #pragma unroll
            for (int c = 0; c < 4; c++) sP[tj*4 + c][i0 + r] = s[r][c] * inv;
        }
        __syncthreads();

        u64 oacc[2][2] = {{0ull, 0ull}, {0ull, 0ull}};
        #pragma unroll 8
        for (int k = 0; k < 64; ++k) {
            float2 pv = *(const float2*)&sP[k][pi*2];
            ulonglong2 vv = *(const ulonglong2*)&sv[k][pd*4];
            u64 a0 = dupf(pv.x), a1 = dupf(pv.y);
            fma2(oacc[0][0], a0, vv.x); fma2(oacc[0][1], a0, vv.y);
            fma2(oacc[1][0], a1, vv.x); fma2(oacc[1][1], a1, vv.y);
        }
        #pragma unroll
        for (int pr = 0; pr < 2; pr++) {
            float2 r0 = unpk(oacc[pr][0]);
            float2 r1 = unpk(oacc[pr][1]);
            int i = pi*2 + pr;
            float* dst = g_o + (((size_t)(w << 6) + i) << 8) + h*32 + pd*4;
            *(float4*)dst = make_float4(r0.x, r0.y, r1.x, r1.y);
        }
        __syncthreads();
    }
}

// ---------------------------------------------------------------------------
extern "C" void kernel_launch(void* const* d_in, const int* in_sizes, int n_in,
                              void* d_out, int out_size)
{
    const float* x       = (const float*)d_in[0];
    const float* w_qkv   = (const float*)d_in[1];
    const float* b_qkv   = (const float*)d_in[2];
    const float* w_out   = (const float*)d_in[3];
    const float* b_out   = (const float*)d_in[4];
    const float* pos_enc = (const float*)d_in[5];
    float* out = (float*)d_out;

    gemm_kernel<0><<<dim3(NTOK/128, 6), 256>>>(x, w_qkv, b_qkv, nullptr);
    attn_kernel<<<NWIN, 256>>>(pos_enc);
    gemm_kernel<1><<<dim3(NTOK/128, 2), 256>>>(nullptr, w_out, b_out, out);
}

// round 12
// speedup vs baseline: 2.1706x; 1.0360x over previous
#include <cuda_runtime.h>
#include <cuda_bf16.h>
#include <mma.h>
#include <cstdint>

using namespace nvcuda;

// ---------------------------------------------------------------------------
// ShiftedWindowAttention: B=32, H=W=64, C=256, WS=8, SHIFT=4, HEADS=8, d=32.
// Round 12: fix host-passed __device__ symbol bug (conv kernels wrote through
// host shadow addresses via ATS; device bf16 buffers stayed zero).  All device
// globals are now referenced from device code only.  wmma bf16 hi/lo GEMMs.
// ---------------------------------------------------------------------------

#define NWIN   2048
#define NTOK   131072
#define CDIM   256
#define SCALEF 0.17677669529663687f   // 32^-0.5

__device__ float g_qkv[3u * NWIN * 8 * 64 * 32];      // [sel][w][h][t][d] fp32
__device__ float g_o[(size_t)NTOK * CDIM];            // [w*64+t][c] fp32
__device__ __nv_bfloat16 g_ah[(size_t)NTOK * CDIM];   // A hi (window-order)
__device__ __nv_bfloat16 g_al[(size_t)NTOK * CDIM];   // A lo
__device__ __nv_bfloat16 g_bh[768 * CDIM];            // W hi
__device__ __nv_bfloat16 g_bl[768 * CDIM];            // W lo

typedef unsigned long long u64;

__device__ __forceinline__ int src_index(int m) {
    int w = m >> 6, t = m & 63;
    int b = w >> 6, wi = w & 63;
    int y  = ((wi >> 3) << 3) + (t >> 3);
    int xx = ((wi & 7) << 3) + (t & 7);
    int ys = (y + 4) & 63, xs = (xx + 4) & 63;
    return (b << 12) + (ys << 6) + xs;
}

__device__ __forceinline__ u64 dupf(float x) {
    u64 r; asm("mov.b64 %0, {%1, %1};" : "=l"(r) : "f"(x)); return r;
}
__device__ __forceinline__ void fma2(u64& d, u64 a, u64 b) {
    asm("fma.rn.f32x2 %0, %1, %2, %0;" : "+l"(d) : "l"(a), "l"(b));
}
__device__ __forceinline__ float2 unpk(u64 v) {
    float2 r; asm("mov.b64 {%0, %1}, %2;" : "=f"(r.x), "=f"(r.y) : "l"(v)); return r;
}

// ---------------------------------------------------------------------------
// fp32 -> bf16 hi/lo split converter.  Destinations are device globals chosen
// by SRCMODE *inside device code* (host must never name __device__ symbols).
// SRCMODE 0: src (weights) -> g_bh/g_bl, row-major.
// SRCMODE 1: src (x) gathered via src_index -> g_ah/g_al.
// SRCMODE 2: g_o -> g_ah/g_al, row-major.
// ---------------------------------------------------------------------------
template<int SRCMODE>
__global__ __launch_bounds__(256) void conv_kernel(const float* __restrict__ src)
{
    size_t gid = ((size_t)blockIdx.x * 256 + threadIdx.x) * 8;
    const float* p;
    __nv_bfloat16 *hi, *lo;
    if (SRCMODE == 0)      { p = src + gid;  hi = g_bh; lo = g_bl; }
    else if (SRCMODE == 1) {
        p = src + (size_t)src_index((int)(gid >> 8)) * CDIM + (int)(gid & 255);
        hi = g_ah; lo = g_al;
    } else                 { p = g_o + gid;  hi = g_ah; lo = g_al; }

    float4 v0 = *(const float4*)p;
    float4 v1 = *(const float4*)(p + 4);
    float vv[8] = {v0.x, v0.y, v0.z, v0.w, v1.x, v1.y, v1.z, v1.w};
    __align__(16) __nv_bfloat16 h[8], l[8];
    #pragma unroll
    for (int i = 0; i < 8; i++) {
        h[i] = __float2bfloat16_rn(vv[i]);
        l[i] = __float2bfloat16_rn(vv[i] - __bfloat162float(h[i]));
    }
    *(uint4*)(hi + gid) = *(const uint4*)h;
    *(uint4*)(lo + gid) = *(const uint4*)l;
}

// ---------------------------------------------------------------------------
// wmma GEMM: C[m][n] = sum_k A[m][k]*W[n][k] + bias[n]
// CTA tile 128x64, 8 warps (4 M x 2 N), warp tile 32x32 = 2x2 wmma 16x16x16.
// K chunks of 32; hi/lo split: Ah*Bh + Al*Bh + Ah*Bl.
// MODE 0: out -> g_qkv layout.  MODE 1: out -> d_out via src_index scatter.
// ---------------------------------------------------------------------------
template<int MODE>
__global__ __launch_bounds__(256) void wmma_gemm(
    const float* __restrict__ bias, float* __restrict__ out)
{
    __shared__ __align__(256) char buf[32768];
    __nv_bfloat16* sAh = (__nv_bfloat16*)(buf);            // 128*40*2 = 10240
    __nv_bfloat16* sAl = (__nv_bfloat16*)(buf + 10240);    // 10240
    __nv_bfloat16* sBh = (__nv_bfloat16*)(buf + 20480);    // 64*40*2 = 5120
    __nv_bfloat16* sBl = (__nv_bfloat16*)(buf + 25600);    // 5120

    const int tid = threadIdx.x, lane = tid & 31, wid = tid >> 5;
    const int m0 = blockIdx.x * 128, n0 = blockIdx.y * 64;
    const int wm = wid & 3, wn = wid >> 2;     // warp tile: rows wm*32, cols wn*32

    wmma::fragment<wmma::accumulator, 16, 16, 16, float> acc[2][2];
    #pragma unroll
    for (int i = 0; i < 2; i++)
        #pragma unroll
        for (int j = 0; j < 2; j++) wmma::fill_fragment(acc[i][j], 0.0f);

    #pragma unroll 1
    for (int c = 0; c < 8; ++c) {
        const int k0 = c * 32;
        #pragma unroll
        for (int idx = tid; idx < 512; idx += 256) {     // A: 128 rows x 4 segs
            int row = idx >> 2, seg = idx & 3;
            size_t ga = (size_t)(m0 + row) * CDIM + k0 + seg * 8;
            int so = row * 40 + seg * 8;
            *(uint4*)(sAh + so) = *(const uint4*)(g_ah + ga);
            *(uint4*)(sAl + so) = *(const uint4*)(g_al + ga);
        }
        {                                                // B: 64 rows x 4 segs
            int row = tid >> 2, seg = tid & 3;
            size_t gb = (size_t)(n0 + row) * CDIM + k0 + seg * 8;
            int so = row * 40 + seg * 8;
            *(uint4*)(sBh + so) = *(const uint4*)(g_bh + gb);
            *(uint4*)(sBl + so) = *(const uint4*)(g_bl + gb);
        }
        __syncthreads();

        #pragma unroll
        for (int ks = 0; ks < 2; ++ks) {
            const int ko = ks * 16;
            wmma::fragment<wmma::matrix_a, 16, 16, 16, __nv_bfloat16, wmma::row_major> fah[2], fal[2];
            wmma::fragment<wmma::matrix_b, 16, 16, 16, __nv_bfloat16, wmma::col_major> fb[2];
            #pragma unroll
            for (int i = 0; i < 2; i++) {
                wmma::load_matrix_sync(fah[i], sAh + (wm * 32 + i * 16) * 40 + ko, 40);
                wmma::load_matrix_sync(fal[i], sAl + (wm * 32 + i * 16) * 40 + ko, 40);
            }
            #pragma unroll
            for (int j = 0; j < 2; j++)
                wmma::load_matrix_sync(fb[j], sBh + (wn * 32 + j * 16) * 40 + ko, 40);
            #pragma unroll
            for (int i = 0; i < 2; i++)
                #pragma unroll
                for (int j = 0; j < 2; j++) {
                    wmma::mma_sync(acc[i][j], fah[i], fb[j], acc[i][j]);
                    wmma::mma_sync(acc[i][j], fal[i], fb[j], acc[i][j]);
                }
            #pragma unroll
            for (int j = 0; j < 2; j++)
                wmma::load_matrix_sync(fb[j], sBl + (wn * 32 + j * 16) * 40 + ko, 40);
            #pragma unroll
            for (int i = 0; i < 2; i++)
                #pragma unroll
                for (int j = 0; j < 2; j++)
                    wmma::mma_sync(acc[i][j], fah[i], fb[j], acc[i][j]);
        }
        __syncthreads();
    }

    // epilogue: stage warp tile (32x32 f32) in smem, then scatter with bias
    float* stg = (float*)(buf) + wid * 1024;
    #pragma unroll
    for (int i = 0; i < 2; i++)
        #pragma unroll
        for (int j = 0; j < 2; j++)
            wmma::store_matrix_sync(stg + i * 16 * 32 + j * 16, acc[i][j], 32,
                                    wmma::mem_row_major);
    __syncwarp();

    const int m = m0 + wm * 32 + lane;
    const int colb = n0 + wn * 32;           // multiple of 32
    float* dst;
    if (MODE == 0) {
        int w = m >> 6, tok = m & 63;
        int sel = colb >> 8, h = (colb >> 5) & 7;
        dst = g_qkv + ((((size_t)(sel * NWIN + w) * 8 + h) << 6) + tok) * 32;
    } else {
        dst = out + (size_t)src_index(m) * CDIM + colb;
    }
    #pragma unroll
    for (int cq = 0; cq < 32; cq += 4) {
        float4 v  = *(float4*)(stg + lane * 32 + cq);
        float4 bv = *(const float4*)(bias + colb + cq);
        v.x += bv.x; v.y += bv.y; v.z += bv.z; v.w += bv.w;
        *(float4*)(dst + cq) = v;
    }
}

// ---------------------------------------------------------------------------
// Attention: 1 CTA / window, 256 threads, loop 8 heads.  (unchanged)
// ---------------------------------------------------------------------------
__global__ __launch_bounds__(256) void attn_kernel(const float* __restrict__ pos_enc)
{
    __shared__ __align__(16) float sqT[32][68];
    __shared__ __align__(16) float skT[32][68];
    __shared__ __align__(16) float sv[64][32];
    __shared__ __align__(16) float sP[64][66];
    __shared__ float spe[232];
    __shared__ int   sreg[64];

    const int w = blockIdx.x, tid = threadIdx.x;
    const int wi = w & 63, wy = wi >> 3, wx = wi & 7;

    if (tid < 64) {
        int y  = wy*8 + (tid >> 3), xx = wx*8 + (tid & 7);
        int by = (y  < 56) ? 0 : (y  < 60 ? 1 : 2);
        int bx = (xx < 56) ? 0 : (xx < 60 ? 1 : 2);
        sreg[tid] = by*3 + bx;
    }

    const int ldr_t = tid >> 2, ldr_d = (tid & 3) * 8;
    const int ti = tid >> 4, tj = tid & 15;
    const int pi = tid >> 3, pd = tid & 7;

    const int i0 = ti * 4;
    int yi[4], xi[4], ri[4];
    #pragma unroll
    for (int r = 0; r < 4; r++) { yi[r] = (i0+r) >> 3; xi[r] = (i0+r) & 7; }

    for (int h = 0; h < 8; ++h) {
        const float* qb = g_qkv + ((size_t)(w*8 + h) << 11);
        const float* kb = qb + (((size_t)NWIN*8) << 11);
        const float* vb = kb + (((size_t)NWIN*8) << 11);

        {
            float4 q0 = *(const float4*)(qb + tid*8);
            float4 q1 = *(const float4*)(qb + tid*8 + 4);
            float4 k0 = *(const float4*)(kb + tid*8);
            float4 k1 = *(const float4*)(kb + tid*8 + 4);
            float4 v0 = *(const float4*)(vb + tid*8);
            float4 v1 = *(const float4*)(vb + tid*8 + 4);
            sqT[ldr_d+0][ldr_t]=q0.x*SCALEF; sqT[ldr_d+1][ldr_t]=q0.y*SCALEF;
            sqT[ldr_d+2][ldr_t]=q0.z*SCALEF; sqT[ldr_d+3][ldr_t]=q0.w*SCALEF;
            sqT[ldr_d+4][ldr_t]=q1.x*SCALEF; sqT[ldr_d+5][ldr_t]=q1.y*SCALEF;
            sqT[ldr_d+6][ldr_t]=q1.z*SCALEF; sqT[ldr_d+7][ldr_t]=q1.w*SCALEF;
            skT[ldr_d+0][ldr_t]=k0.x; skT[ldr_d+1][ldr_t]=k0.y;
            skT[ldr_d+2][ldr_t]=k0.z; skT[ldr_d+3][ldr_t]=k0.w;
            skT[ldr_d+4][ldr_t]=k1.x; skT[ldr_d+5][ldr_t]=k1.y;
            skT[ldr_d+6][ldr_t]=k1.z; skT[ldr_d+7][ldr_t]=k1.w;
            *(float4*)&sv[ldr_t][ldr_d]     = v0;
            *(float4*)&sv[ldr_t][ldr_d + 4] = v1;
            if (tid < 225) spe[tid] = pos_enc[h*225 + tid];
        }
        __syncthreads();

        u64 sacc[4][2];
        #pragma unroll
        for (int r = 0; r < 4; r++) { sacc[r][0] = 0ull; sacc[r][1] = 0ull; }
        #pragma unroll 8
        for (int d = 0; d < 32; ++d) {
            float4 av = *(const float4*)&sqT[d][i0];
            ulonglong2 bv = *(const ulonglong2*)&skT[d][tj*4];
            u64 aa[4] = {dupf(av.x), dupf(av.y), dupf(av.z), dupf(av.w)};
            #pragma unroll
            for (int r = 0; r < 4; r++) {
                fma2(sacc[r][0], aa[r], bv.x);
                fma2(sacc[r][1], aa[r], bv.y);
            }
        }

        float s[4][4];
        #pragma unroll
        for (int r = 0; r < 4; r++) {
            float2 v0 = unpk(sacc[r][0]), v1 = unpk(sacc[r][1]);
            s[r][0] = v0.x; s[r][1] = v0.y; s[r][2] = v1.x; s[r][3] = v1.y;
        }
        #pragma unroll
        for (int r = 0; r < 4; r++) ri[r] = sreg[i0 + r];
        #pragma unroll
        for (int c = 0; c < 4; c++) {
            int j = tj*4 + c;
            int yj = j >> 3, xj = j & 7, rj = sreg[j];
            #pragma unroll
            for (int r = 0; r < 4; r++) {
                float val = s[r][c] + spe[(yi[r]-yj+7)*15 + (xi[r]-xj+7)];
                s[r][c] = (rj != ri[r]) ? -1e30f : val;
            }
        }
        #pragma unroll
        for (int r = 0; r < 4; r++) {
            float mx = fmaxf(fmaxf(s[r][0], s[r][1]), fmaxf(s[r][2], s[r][3]));
            mx = fmaxf(mx, __shfl_xor_sync(0xffffffffu, mx, 1));
            mx = fmaxf(mx, __shfl_xor_sync(0xffffffffu, mx, 2));
            mx = fmaxf(mx, __shfl_xor_sync(0xffffffffu, mx, 4));
            mx = fmaxf(mx, __shfl_xor_sync(0xffffffffu, mx, 8));
            float sum = 0.f;
            #pragma unroll
            for (int c = 0; c < 4; c++) { s[r][c] = __expf(s[r][c] - mx); sum += s[r][c]; }
            sum += __shfl_xor_sync(0xffffffffu, sum, 1);
            sum += __shfl_xor_sync(0xffffffffu, sum, 2);
            sum += __shfl_xor_sync(0xffffffffu, sum, 4);
            sum += __shfl_xor_sync(0xffffffffu, sum, 8);
            float inv = 1.0f / sum;
            #pragma unroll
            for (int c = 0; c < 4; c++) sP[tj*4 + c][i0 + r] = s[r][c] * inv;
        }
        __syncthreads();

        u64 oacc[2][2] = {{0ull, 0ull}, {0ull, 0ull}};
        #pragma unroll 8
        for (int k = 0; k < 64; ++k) {
            float2 pv = *(const float2*)&sP[k][pi*2];
            ulonglong2 vv = *(const ulonglong2*)&sv[k][pd*4];
            u64 a0 = dupf(pv.x), a1 = dupf(pv.y);
            fma2(oacc[0][0], a0, vv.x); fma2(oacc[0][1], a0, vv.y);
            fma2(oacc[1][0], a1, vv.x); fma2(oacc[1][1], a1, vv.y);
        }
        #pragma unroll
        for (int pr = 0; pr < 2; pr++) {
            float2 r0 = unpk(oacc[pr][0]);
            float2 r1 = unpk(oacc[pr][1]);
            int i = pi*2 + pr;
            float* dst = g_o + (((size_t)(w << 6) + i) << 8) + h*32 + pd*4;
            *(float4*)dst = make_float4(r0.x, r0.y, r1.x, r1.y);
        }
        __syncthreads();
    }
}

// ---------------------------------------------------------------------------
extern "C" void kernel_launch(void* const* d_in, const int* in_sizes, int n_in,
                              void* d_out, int out_size)
{
    const float* x       = (const float*)d_in[0];
    const float* w_qkv   = (const float*)d_in[1];
    const float* b_qkv   = (const float*)d_in[2];
    const float* w_out   = (const float*)d_in[3];
    const float* b_out   = (const float*)d_in[4];
    const float* pos_enc = (const float*)d_in[5];
    float* out = (float*)d_out;

    // bf16 hi/lo splits (destinations are device globals inside the kernels)
    conv_kernel<1><<<16384, 256>>>(x);        // gathered X -> g_ah/g_al
    conv_kernel<0><<<96,    256>>>(w_qkv);    // w_qkv -> g_bh/g_bl (768 rows)
    // QKV GEMM -> g_qkv
    wmma_gemm<0><<<dim3(1024, 12), 256>>>(b_qkv, nullptr);
    // attention -> g_o
    attn_kernel<<<NWIN, 256>>>(pos_enc);
    // proj inputs
    conv_kernel<2><<<16384, 256>>>(nullptr);  // g_o -> g_ah/g_al
    conv_kernel<0><<<32,    256>>>(w_out);    // w_out -> g_bh/g_bl (256 rows)
    // out projection -> d_out (scatter)
    wmma_gemm<1><<<dim3(1024, 4), 256>>>(b_out, out);
}

// round 14
// speedup vs baseline: 2.2731x; 1.0472x over previous
#include <cuda_runtime.h>
#include <cuda_bf16.h>
#include <mma.h>
#include <cstdint>

using namespace nvcuda;

// ---------------------------------------------------------------------------
// ShiftedWindowAttention: B=32, H=W=64, C=256, WS=8, SHIFT=4, HEADS=8, d=32.
// Round 13: (a) grid swap on wmma GEMMs so A-tile-sharing CTAs are launch-
// adjacent (L2 reuse: qkv A traffic 3.2GB -> 268MB); (b) attention writes
// bf16 hi/lo directly (conv<2> eliminated, g_o eliminated).
// ---------------------------------------------------------------------------

#define NWIN   2048
#define NTOK   131072
#define CDIM   256
#define SCALEF 0.17677669529663687f   // 32^-0.5

__device__ float g_qkv[3u * NWIN * 8 * 64 * 32];      // [sel][w][h][t][d] fp32
__device__ __nv_bfloat16 g_ah[(size_t)NTOK * CDIM];   // A hi (window-order)
__device__ __nv_bfloat16 g_al[(size_t)NTOK * CDIM];   // A lo
__device__ __nv_bfloat16 g_bh[768 * CDIM];            // W hi
__device__ __nv_bfloat16 g_bl[768 * CDIM];            // W lo

typedef unsigned long long u64;

__device__ __forceinline__ int src_index(int m) {
    int w = m >> 6, t = m & 63;
    int b = w >> 6, wi = w & 63;
    int y  = ((wi >> 3) << 3) + (t >> 3);
    int xx = ((wi & 7) << 3) + (t & 7);
    int ys = (y + 4) & 63, xs = (xx + 4) & 63;
    return (b << 12) + (ys << 6) + xs;
}

__device__ __forceinline__ u64 dupf(float x) {
    u64 r; asm("mov.b64 %0, {%1, %1};" : "=l"(r) : "f"(x)); return r;
}
__device__ __forceinline__ void fma2(u64& d, u64 a, u64 b) {
    asm("fma.rn.f32x2 %0, %1, %2, %0;" : "+l"(d) : "l"(a), "l"(b));
}
__device__ __forceinline__ float2 unpk(u64 v) {
    float2 r; asm("mov.b64 {%0, %1}, %2;" : "=f"(r.x), "=f"(r.y) : "l"(v)); return r;
}

// ---------------------------------------------------------------------------
// fp32 -> bf16 hi/lo split converter (destinations chosen in device code).
// SRCMODE 0: src (weights) -> g_bh/g_bl, row-major.
// SRCMODE 1: src (x) gathered via src_index -> g_ah/g_al.
// ---------------------------------------------------------------------------
template<int SRCMODE>
__global__ __launch_bounds__(256) void conv_kernel(const float* __restrict__ src)
{
    size_t gid = ((size_t)blockIdx.x * 256 + threadIdx.x) * 8;
    const float* p;
    __nv_bfloat16 *hi, *lo;
    if (SRCMODE == 0)      { p = src + gid;  hi = g_bh; lo = g_bl; }
    else {
        p = src + (size_t)src_index((int)(gid >> 8)) * CDIM + (int)(gid & 255);
        hi = g_ah; lo = g_al;
    }

    float4 v0 = *(const float4*)p;
    float4 v1 = *(const float4*)(p + 4);
    float vv[8] = {v0.x, v0.y, v0.z, v0.w, v1.x, v1.y, v1.z, v1.w};
    __align__(16) __nv_bfloat16 h[8], l[8];
    #pragma unroll
    for (int i = 0; i < 8; i++) {
        h[i] = __float2bfloat16_rn(vv[i]);
        l[i] = __float2bfloat16_rn(vv[i] - __bfloat162float(h[i]));
    }
    *(uint4*)(hi + gid) = *(const uint4*)h;
    *(uint4*)(lo + gid) = *(const uint4*)l;
}

// ---------------------------------------------------------------------------
// wmma GEMM: C[m][n] = sum_k A[m][k]*W[n][k] + bias[n]
// CTA tile 128x64, 8 warps (4 M x 2 N), warp tile 32x32 = 2x2 wmma 16x16x16.
// K chunks of 32; hi/lo split: Ah*Bh + Al*Bh + Ah*Bl.
// GRID: blockIdx.x = n-tile (fast-varying -> A-tile L2 sharing),
//       blockIdx.y = m-tile.
// MODE 0: out -> g_qkv layout.  MODE 1: out -> d_out via src_index scatter.
// ---------------------------------------------------------------------------
template<int MODE>
__global__ __launch_bounds__(256) void wmma_gemm(
    const float* __restrict__ bias, float* __restrict__ out)
{
    __shared__ __align__(256) char buf[32768];
    __nv_bfloat16* sAh = (__nv_bfloat16*)(buf);            // 128*40*2 = 10240
    __nv_bfloat16* sAl = (__nv_bfloat16*)(buf + 10240);    // 10240
    __nv_bfloat16* sBh = (__nv_bfloat16*)(buf + 20480);    // 64*40*2 = 5120
    __nv_bfloat16* sBl = (__nv_bfloat16*)(buf + 25600);    // 5120

    const int tid = threadIdx.x, lane = tid & 31, wid = tid >> 5;
    const int m0 = blockIdx.y * 128, n0 = blockIdx.x * 64;
    const int wm = wid & 3, wn = wid >> 2;     // warp tile: rows wm*32, cols wn*32

    wmma::fragment<wmma::accumulator, 16, 16, 16, float> acc[2][2];
    #pragma unroll
    for (int i = 0; i < 2; i++)
        #pragma unroll
        for (int j = 0; j < 2; j++) wmma::fill_fragment(acc[i][j], 0.0f);

    #pragma unroll 1
    for (int c = 0; c < 8; ++c) {
        const int k0 = c * 32;
        #pragma unroll
        for (int idx = tid; idx < 512; idx += 256) {     // A: 128 rows x 4 segs
            int row = idx >> 2, seg = idx & 3;
            size_t ga = (size_t)(m0 + row) * CDIM + k0 + seg * 8;
            int so = row * 40 + seg * 8;
            *(uint4*)(sAh + so) = *(const uint4*)(g_ah + ga);
            *(uint4*)(sAl + so) = *(const uint4*)(g_al + ga);
        }
        {                                                // B: 64 rows x 4 segs
            int row = tid >> 2, seg = tid & 3;
            size_t gb = (size_t)(n0 + row) * CDIM + k0 + seg * 8;
            int so = row * 40 + seg * 8;
            *(uint4*)(sBh + so) = *(const uint4*)(g_bh + gb);
            *(uint4*)(sBl + so) = *(const uint4*)(g_bl + gb);
        }
        __syncthreads();

        #pragma unroll
        for (int ks = 0; ks < 2; ++ks) {
            const int ko = ks * 16;
            wmma::fragment<wmma::matrix_a, 16, 16, 16, __nv_bfloat16, wmma::row_major> fah[2], fal[2];
            wmma::fragment<wmma::matrix_b, 16, 16, 16, __nv_bfloat16, wmma::col_major> fb[2];
            #pragma unroll
            for (int i = 0; i < 2; i++) {
                wmma::load_matrix_sync(fah[i], sAh + (wm * 32 + i * 16) * 40 + ko, 40);
                wmma::load_matrix_sync(fal[i], sAl + (wm * 32 + i * 16) * 40 + ko, 40);
            }
            #pragma unroll
            for (int j = 0; j < 2; j++)
                wmma::load_matrix_sync(fb[j], sBh + (wn * 32 + j * 16) * 40 + ko, 40);
            #pragma unroll
            for (int i = 0; i < 2; i++)
                #pragma unroll
                for (int j = 0; j < 2; j++) {
                    wmma::mma_sync(acc[i][j], fah[i], fb[j], acc[i][j]);
                    wmma::mma_sync(acc[i][j], fal[i], fb[j], acc[i][j]);
                }
            #pragma unroll
            for (int j = 0; j < 2; j++)
                wmma::load_matrix_sync(fb[j], sBl + (wn * 32 + j * 16) * 40 + ko, 40);
            #pragma unroll
            for (int i = 0; i < 2; i++)
                #pragma unroll
                for (int j = 0; j < 2; j++)
                    wmma::mma_sync(acc[i][j], fah[i], fb[j], acc[i][j]);
        }
        __syncthreads();
    }

    // epilogue: stage warp tile (32x32 f32) in smem, then scatter with bias
    float* stg = (float*)(buf) + wid * 1024;
    #pragma unroll
    for (int i = 0; i < 2; i++)
        #pragma unroll
        for (int j = 0; j < 2; j++)
            wmma::store_matrix_sync(stg + i * 16 * 32 + j * 16, acc[i][j], 32,
                                    wmma::mem_row_major);
    __syncwarp();

    const int m = m0 + wm * 32 + lane;
    const int colb = n0 + wn * 32;           // multiple of 32
    float* dst;
    if (MODE == 0) {
        int w = m >> 6, tok = m & 63;
        int sel = colb >> 8, h = (colb >> 5) & 7;
        dst = g_qkv + ((((size_t)(sel * NWIN + w) * 8 + h) << 6) + tok) * 32;
    } else {
        dst = out + (size_t)src_index(m) * CDIM + colb;
    }
    #pragma unroll
    for (int cq = 0; cq < 32; cq += 4) {
        float4 v  = *(float4*)(stg + lane * 32 + cq);
        float4 bv = *(const float4*)(bias + colb + cq);
        v.x += bv.x; v.y += bv.y; v.z += bv.z; v.w += bv.w;
        *(float4*)(dst + cq) = v;
    }
}

// ---------------------------------------------------------------------------
// Attention: 1 CTA / window, 256 threads, loop 8 heads.
// Epilogue now writes bf16 hi/lo directly into g_ah/g_al (proj GEMM inputs).
// ---------------------------------------------------------------------------
__global__ __launch_bounds__(256) void attn_kernel(const float* __restrict__ pos_enc)
{
    __shared__ __align__(16) float sqT[32][68];
    __shared__ __align__(16) float skT[32][68];
    __shared__ __align__(16) float sv[64][32];
    __shared__ __align__(16) float sP[64][66];
    __shared__ float spe[232];
    __shared__ int   sreg[64];

    const int w = blockIdx.x, tid = threadIdx.x;
    const int wi = w & 63, wy = wi >> 3, wx = wi & 7;

    if (tid < 64) {
        int y  = wy*8 + (tid >> 3), xx = wx*8 + (tid & 7);
        int by = (y  < 56) ? 0 : (y  < 60 ? 1 : 2);
        int bx = (xx < 56) ? 0 : (xx < 60 ? 1 : 2);
        sreg[tid] = by*3 + bx;
    }

    const int ldr_t = tid >> 2, ldr_d = (tid & 3) * 8;
    const int ti = tid >> 4, tj = tid & 15;
    const int pi = tid >> 3, pd = tid & 7;

    const int i0 = ti * 4;
    int yi[4], xi[4], ri[4];
    #pragma unroll
    for (int r = 0; r < 4; r++) { yi[r] = (i0+r) >> 3; xi[r] = (i0+r) & 7; }

    for (int h = 0; h < 8; ++h) {
        const float* qb = g_qkv + ((size_t)(w*8 + h) << 11);
        const float* kb = qb + (((size_t)NWIN*8) << 11);
        const float* vb = kb + (((size_t)NWIN*8) << 11);

        {
            float4 q0 = *(const float4*)(qb + tid*8);
            float4 q1 = *(const float4*)(qb + tid*8 + 4);
            float4 k0 = *(const float4*)(kb + tid*8);
            float4 k1 = *(const float4*)(kb + tid*8 + 4);
            float4 v0 = *(const float4*)(vb + tid*8);
            float4 v1 = *(const float4*)(vb + tid*8 + 4);
            sqT[ldr_d+0][ldr_t]=q0.x*SCALEF; sqT[ldr_d+1][ldr_t]=q0.y*SCALEF;
            sqT[ldr_d+2][ldr_t]=q0.z*SCALEF; sqT[ldr_d+3][ldr_t]=q0.w*SCALEF;
            sqT[ldr_d+4][ldr_t]=q1.x*SCALEF; sqT[ldr_d+5][ldr_t]=q1.y*SCALEF;
            sqT[ldr_d+6][ldr_t]=q1.z*SCALEF; sqT[ldr_d+7][ldr_t]=q1.w*SCALEF;
            skT[ldr_d+0][ldr_t]=k0.x; skT[ldr_d+1][ldr_t]=k0.y;
            skT[ldr_d+2][ldr_t]=k0.z; skT[ldr_d+3][ldr_t]=k0.w;
            skT[ldr_d+4][ldr_t]=k1.x; skT[ldr_d+5][ldr_t]=k1.y;
            skT[ldr_d+6][ldr_t]=k1.z; skT[ldr_d+7][ldr_t]=k1.w;
            *(float4*)&sv[ldr_t][ldr_d]     = v0;
            *(float4*)&sv[ldr_t][ldr_d + 4] = v1;
            if (tid < 225) spe[tid] = pos_enc[h*225 + tid];
        }
        __syncthreads();

        u64 sacc[4][2];
        #pragma unroll
        for (int r = 0; r < 4; r++) { sacc[r][0] = 0ull; sacc[r][1] = 0ull; }
        #pragma unroll 8
        for (int d = 0; d < 32; ++d) {
            float4 av = *(const float4*)&sqT[d][i0];
            ulonglong2 bv = *(const ulonglong2*)&skT[d][tj*4];
            u64 aa[4] = {dupf(av.x), dupf(av.y), dupf(av.z), dupf(av.w)};
            #pragma unroll
            for (int r = 0; r < 4; r++) {
                fma2(sacc[r][0], aa[r], bv.x);
                fma2(sacc[r][1], aa[r], bv.y);
            }
        }

        float s[4][4];
        #pragma unroll
        for (int r = 0; r < 4; r++) {
            float2 v0 = unpk(sacc[r][0]), v1 = unpk(sacc[r][1]);
            s[r][0] = v0.x; s[r][1] = v0.y; s[r][2] = v1.x; s[r][3] = v1.y;
        }
        #pragma unroll
        for (int r = 0; r < 4; r++) ri[r] = sreg[i0 + r];
        #pragma unroll
        for (int c = 0; c < 4; c++) {
            int j = tj*4 + c;
            int yj = j >> 3, xj = j & 7, rj = sreg[j];
            #pragma unroll
            for (int r = 0; r < 4; r++) {
                float val = s[r][c] + spe[(yi[r]-yj+7)*15 + (xi[r]-xj+7)];
                s[r][c] = (rj != ri[r]) ? -1e30f : val;
            }
        }
        #pragma unroll
        for (int r = 0; r < 4; r++) {
            float mx = fmaxf(fmaxf(s[r][0], s[r][1]), fmaxf(s[r][2], s[r][3]));
            mx = fmaxf(mx, __shfl_xor_sync(0xffffffffu, mx, 1));
            mx = fmaxf(mx, __shfl_xor_sync(0xffffffffu, mx, 2));
            mx = fmaxf(mx, __shfl_xor_sync(0xffffffffu, mx, 4));
            mx = fmaxf(mx, __shfl_xor_sync(0xffffffffu, mx, 8));
            float sum = 0.f;
            #pragma unroll
            for (int c = 0; c < 4; c++) { s[r][c] = __expf(s[r][c] - mx); sum += s[r][c]; }
            sum += __shfl_xor_sync(0xffffffffu, sum, 1);
            sum += __shfl_xor_sync(0xffffffffu, sum, 2);
            sum += __shfl_xor_sync(0xffffffffu, sum, 4);
            sum += __shfl_xor_sync(0xffffffffu, sum, 8);
            float inv = 1.0f / sum;
            #pragma unroll
            for (int c = 0; c < 4; c++) sP[tj*4 + c][i0 + r] = s[r][c] * inv;
        }
        __syncthreads();

        u64 oacc[2][2] = {{0ull, 0ull}, {0ull, 0ull}};
        #pragma unroll 8
        for (int k = 0; k < 64; ++k) {
            float2 pv = *(const float2*)&sP[k][pi*2];
            ulonglong2 vv = *(const ulonglong2*)&sv[k][pd*4];
            u64 a0 = dupf(pv.x), a1 = dupf(pv.y);
            fma2(oacc[0][0], a0, vv.x); fma2(oacc[0][1], a0, vv.y);
            fma2(oacc[1][0], a1, vv.x); fma2(oacc[1][1], a1, vv.y);
        }
        #pragma unroll
        for (int pr = 0; pr < 2; pr++) {
            float2 r0 = unpk(oacc[pr][0]);
            float2 r1 = unpk(oacc[pr][1]);
            int i = pi*2 + pr;
            float vals[4] = {r0.x, r0.y, r1.x, r1.y};
            __align__(8) __nv_bfloat16 hb[4], lb[4];
            #pragma unroll
            for (int q = 0; q < 4; q++) {
                hb[q] = __float2bfloat16_rn(vals[q]);
                lb[q] = __float2bfloat16_rn(vals[q] - __bfloat162float(hb[q]));
            }
            size_t off = (((size_t)(w << 6) + i) << 8) + h*32 + pd*4;
            *(uint2*)(g_ah + off) = *(const uint2*)hb;
            *(uint2*)(g_al + off) = *(const uint2*)lb;
        }
        __syncthreads();
    }
}

// ---------------------------------------------------------------------------
extern "C" void kernel_launch(void* const* d_in, const int* in_sizes, int n_in,
                              void* d_out, int out_size)
{
    const float* x       = (const float*)d_in[0];
    const float* w_qkv   = (const float*)d_in[1];
    const float* b_qkv   = (const float*)d_in[2];
    const float* w_out   = (const float*)d_in[3];
    const float* b_out   = (const float*)d_in[4];
    const float* pos_enc = (const float*)d_in[5];
    float* out = (float*)d_out;

    // bf16 hi/lo splits
    conv_kernel<1><<<16384, 256>>>(x);        // gathered X -> g_ah/g_al
    conv_kernel<0><<<96,    256>>>(w_qkv);    // w_qkv -> g_bh/g_bl
    // QKV GEMM -> g_qkv   (n-tiles on x for A-tile L2 sharing)
    wmma_gemm<0><<<dim3(12, 1024), 256>>>(b_qkv, nullptr);
    // attention -> g_ah/g_al (bf16 hi/lo, proj inputs)
    attn_kernel<<<NWIN, 256>>>(pos_enc);
    // proj weights
    conv_kernel<0><<<32, 256>>>(w_out);       // w_out -> g_bh/g_bl
    // out projection -> d_out (scatter)
    wmma_gemm<1><<<dim3(4, 1024), 256>>>(b_out, out);
}